// round 2
// baseline (speedup 1.0000x reference)
#include <cuda_runtime.h>
#include <math.h>

// StructureLoss: B=32, C=1, H=W=512 fp32.
// out = mean_b( wbce_b + wiou_b )
//   weit = 1 + 5*|boxavg31(t) - t|   (zero-padded sum / 961)
//   bce  = max(x,0) - x*t + log1p(exp(-|x|))
//   wbce = sum(weit*bce)/sum(weit)
//   p = sigmoid(x); inter = sum(p*t*weit); union = sum((p+t)*weit)
//   wiou = 1 - (inter+1)/(union-inter+1)

#define BATCH 32
#define Hdim 512
#define Wdim 512
#define KR 15            // radius
#define TW 128           // output columns per block
#define NT 160           // threads = TW + 2*16 halo (5 warps)
#define SEG 128          // rows per block segment

// per-image accumulators: [b][0]=sum(weit*bce) [1]=sum(weit) [2]=inter [3]=union
__device__ float g_acc[BATCH * 4];

__global__ void zero_acc_kernel() {
    int i = threadIdx.x;
    if (i < BATCH * 4) g_acc[i] = 0.0f;
}

__global__ __launch_bounds__(NT) void structloss_main(
    const float* __restrict__ x, const float* __restrict__ t)
{
    __shared__ float sP[2][NT];      // inclusive prefix of vertical sums (double buffered)
    __shared__ float sW[2][8];       // per-warp scan totals (double buffered)
    __shared__ float rsum[5][4];     // block-reduce scratch

    const int i     = threadIdx.x;           // 0..159
    const int lid   = i & 31;
    const int wid   = i >> 5;                // 0..4
    const int strip = blockIdx.x;            // 0..3
    const int seg   = blockIdx.y;            // 0..3
    const int b     = blockIdx.z;            // 0..31

    const int c0 = strip * TW;
    const int gc = c0 + i - 16;              // global column of this thread's vertical sum
    const bool colok = (gc >= 0) && (gc < Wdim);
    const int R0 = seg * SEG;

    const float* __restrict__ tb = t + (size_t)b * Hdim * Wdim;
    const float* __restrict__ xb = x + (size_t)b * Hdim * Wdim;

    // ---- prologue: vs = sum of t rows [R0-15, R0+14] for this column ----
    float vs = 0.0f;
    #pragma unroll 5
    for (int r = R0 - KR; r < R0 + KR; ++r) {
        float v = (colok && r >= 0 && r < Hdim) ? tb[r * Wdim + gc] : 0.0f;
        vs += v;
    }

    const bool outok = (i >= 16) && (i < 16 + TW);

    float a_wb = 0.0f, a_w = 0.0f, a_i = 0.0f, a_u = 0.0f;

    for (int r = R0; r < R0 + SEG; ++r) {
        // slide window down: add row r+15 -> vs = sum rows [r-15, r+15]
        float tn = (colok && (r + KR) < Hdim) ? tb[(r + KR) * Wdim + gc] : 0.0f;
        vs += tn;

        const int buf = r & 1;

        // ---- block-wide inclusive prefix scan of vs across the 160 columns ----
        float s = vs;
        #pragma unroll
        for (int o = 1; o < 32; o <<= 1) {
            float n = __shfl_up_sync(0xffffffffu, s, o);
            if (lid >= o) s += n;
        }
        if (lid == 31) sW[buf][wid] = s;
        __syncthreads();
        {
            const float w0 = sW[buf][0], w1 = sW[buf][1], w2 = sW[buf][2], w3 = sW[buf][3];
            float off = 0.0f;
            if (wid > 0) off += w0;
            if (wid > 1) off += w1;
            if (wid > 2) off += w2;
            if (wid > 3) off += w3;
            sP[buf][i] = s + off;
        }
        __syncthreads();

        if (outok) {
            // 31x31 box sum = prefix difference of vertical sums
            const float h   = sP[buf][i + 15] - sP[buf][i - 16];
            const float avg = h * (1.0f / 961.0f);

            const float tt = tb[r * Wdim + gc];      // cache hit (loaded 15 rows ago)
            const float w  = 1.0f + 5.0f * fabsf(avg - tt);

            const float xx = xb[r * Wdim + gc];
            const float ax = fabsf(xx);
            const float e  = __expf(-ax);            // MUFU EX2
            const float d  = 1.0f + e;               // in (1, 2]
            const float L  = __logf(d);              // MUFU LG2 : log1p(e)

            // fast reciprocal of d in (1,2]: bit-hack + 2 Newton (err ~6e-6)
            float rcp = __uint_as_float(0x7EF311C3u - __float_as_uint(d));
            rcp = rcp * (2.0f - d * rcp);
            rcp = rcp * (2.0f - d * rcp);

            const float bce = fmaxf(xx, 0.0f) - xx * tt + L;
            const float p   = (xx >= 0.0f) ? rcp : e * rcp;   // sigmoid(x)

            a_wb += w * bce;
            a_w  += w;
            a_i  += p * tt * w;
            a_u  += (p + tt) * w;
        }

        // remove row r-15
        float to = (colok && (r - KR) >= 0) ? tb[(r - KR) * Wdim + gc] : 0.0f;
        vs -= to;
    }

    // ---- block reduction of the 4 accumulators ----
    float vals[4] = {a_wb, a_w, a_i, a_u};
    #pragma unroll
    for (int k = 0; k < 4; ++k) {
        float v = vals[k];
        #pragma unroll
        for (int o = 16; o > 0; o >>= 1)
            v += __shfl_down_sync(0xffffffffu, v, o);
        vals[k] = v;
    }
    if (lid == 0) {
        #pragma unroll
        for (int k = 0; k < 4; ++k) rsum[wid][k] = vals[k];
    }
    __syncthreads();
    if (i == 0) {
        #pragma unroll
        for (int k = 0; k < 4; ++k) {
            float s2 = rsum[0][k] + rsum[1][k] + rsum[2][k] + rsum[3][k] + rsum[4][k];
            atomicAdd(&g_acc[b * 4 + k], s2);
        }
    }
}

__global__ void finalize_kernel(float* __restrict__ out) {
    const int b = threadIdx.x;   // 32 threads, one per image
    float v = 0.0f;
    if (b < BATCH) {
        const float swb = g_acc[b * 4 + 0];
        const float sw  = g_acc[b * 4 + 1];
        const float si  = g_acc[b * 4 + 2];
        const float su  = g_acc[b * 4 + 3];
        const float wbce = swb / sw;
        const float wiou = 1.0f - (si + 1.0f) / (su - si + 1.0f);
        v = wbce + wiou;
    }
    #pragma unroll
    for (int o = 16; o > 0; o >>= 1)
        v += __shfl_down_sync(0xffffffffu, v, o);
    if (b == 0) out[0] = v * (1.0f / (float)BATCH);
}

extern "C" void kernel_launch(void* const* d_in, const int* in_sizes, int n_in,
                              void* d_out, int out_size)
{
    const float* x = (const float*)d_in[0];   // input (logits)
    const float* t = (const float*)d_in[1];   // target
    float* out = (float*)d_out;

    zero_acc_kernel<<<1, 128>>>();
    dim3 grid(Wdim / TW, Hdim / SEG, BATCH);  // (4, 4, 32)
    structloss_main<<<grid, NT>>>(x, t);
    finalize_kernel<<<1, 32>>>(out);
}

// round 7
// speedup vs baseline: 2.2699x; 2.2699x over previous
#include <cuda_runtime.h>
#include <math.h>

// StructureLoss: B=32, C=1, H=W=512 fp32.
// out = mean_b( wbce_b + wiou_b )
//   weit = 1 + 5*|boxavg31(t) - t|   (zero-padded sum / 961)
//   bce  = max(x,0) - x*t + log1p(exp(-|x|))
//   wbce = sum(weit*bce)/sum(weit)
//   p = sigmoid(x); inter = sum(p*t*weit); union = sum((p+t)*weit)
//   wiou = 1 - (inter+1)/(union-inter+1)

#define BATCH 32
#define Hdim 512
#define Wdim 512
#define KR 15            // radius
#define TW 128           // output columns per block
#define NT 160           // threads = TW + 2*16 halo (5 warps)
#define SEG 64           // rows per block segment
#define RB 4             // rows per batch (pipelined)
#define NB (SEG / RB)    // batches per segment

// per-image accumulators: [b][0]=sum(weit*bce) [1]=sum(weit) [2]=inter [3]=union
__device__ float g_acc[BATCH * 4];

__global__ void zero_acc_kernel() {
    int i = threadIdx.x;
    if (i < BATCH * 4) g_acc[i] = 0.0f;
}

__global__ __launch_bounds__(NT) void structloss_main(
    const float* __restrict__ x, const float* __restrict__ t)
{
    __shared__ float sP[RB][NT];     // block-wide prefix of vertical sums, 4 rows
    __shared__ float sW[RB][8];      // per-warp scan totals
    __shared__ float rsum[5][4];     // block-reduce scratch

    const int i     = threadIdx.x;           // 0..159
    const int lid   = i & 31;
    const int wid   = i >> 5;                // 0..4
    const int strip = blockIdx.x;            // 0..3
    const int seg   = blockIdx.y;            // 0..7
    const int b     = blockIdx.z;            // 0..31

    const int c0 = strip * TW;
    const int gc = c0 + i - 16;              // global column of this thread's vertical sum
    const bool colok = (gc >= 0) && (gc < Wdim);
    const int R0 = seg * SEG;

    const float* __restrict__ tb = t + (size_t)b * Hdim * Wdim;
    const float* __restrict__ xb = x + (size_t)b * Hdim * Wdim;

    const bool outok = (i >= 16) && (i < 16 + TW);

    // guarded t load at (row r, this thread's column)
    #define LDT(r) ((colok && (unsigned)(r) < (unsigned)Hdim) ? __ldg(&tb[(r) * Wdim + gc]) : 0.0f)

    // ---- prologue: vs = sum of t rows [R0-15, R0+14] (30 independent loads, MLP) ----
    float vs = 0.0f;
    #pragma unroll
    for (int j = 0; j < 2 * KR; ++j) {
        vs += LDT(R0 - KR + j);
    }

    // ---- preload batch 0 ----
    float tn[RB], to[RB], tt[RB], xx[RB];
    #pragma unroll
    for (int j = 0; j < RB; ++j) {
        const int r = R0 + j;
        tn[j] = LDT(r + KR);
        to[j] = LDT(r - KR);
        tt[j] = outok ? __ldg(&tb[r * Wdim + gc]) : 0.0f;
        xx[j] = outok ? __ldg(&xb[r * Wdim + gc]) : 0.0f;
    }

    float a_wb = 0.0f, a_w = 0.0f, a_i = 0.0f, a_u = 0.0f;

    for (int batch = 0; batch < NB; ++batch) {
        const int r0 = R0 + batch * RB;

        // ---- issue next batch's loads first (overlap with scan/math below) ----
        float ntn[RB], nto[RB], ntt[RB], nxx[RB];
        if (batch + 1 < NB) {
            #pragma unroll
            for (int j = 0; j < RB; ++j) {
                const int r = r0 + RB + j;
                ntn[j] = LDT(r + KR);
                nto[j] = LDT(r - KR);
                ntt[j] = outok ? __ldg(&tb[r * Wdim + gc]) : 0.0f;
                nxx[j] = outok ? __ldg(&xb[r * Wdim + gc]) : 0.0f;
            }
        }

        // ---- vertical sliding sums for 4 rows ----
        float s0, s1, s2, s3;
        vs += tn[0]; s0 = vs; vs -= to[0];
        vs += tn[1]; s1 = vs; vs -= to[1];
        vs += tn[2]; s2 = vs; vs -= to[2];
        vs += tn[3]; s3 = vs; vs -= to[3];

        // ---- 4 interleaved warp inclusive scans ----
        #pragma unroll
        for (int o = 1; o < 32; o <<= 1) {
            float n0 = __shfl_up_sync(0xffffffffu, s0, o);
            float n1 = __shfl_up_sync(0xffffffffu, s1, o);
            float n2 = __shfl_up_sync(0xffffffffu, s2, o);
            float n3 = __shfl_up_sync(0xffffffffu, s3, o);
            if (lid >= o) { s0 += n0; s1 += n1; s2 += n2; s3 += n3; }
        }
        if (lid == 31) {
            sW[0][wid] = s0; sW[1][wid] = s1; sW[2][wid] = s2; sW[3][wid] = s3;
        }
        __syncthreads();
        {
            float o0 = 0.0f, o1 = 0.0f, o2 = 0.0f, o3 = 0.0f;
            #pragma unroll
            for (int w = 0; w < 4; ++w) {
                if (wid > w) { o0 += sW[0][w]; o1 += sW[1][w]; o2 += sW[2][w]; o3 += sW[3][w]; }
            }
            sP[0][i] = s0 + o0; sP[1][i] = s1 + o1; sP[2][i] = s2 + o2; sP[3][i] = s3 + o3;
        }
        __syncthreads();

        if (outok) {
            #pragma unroll
            for (int j = 0; j < RB; ++j) {
                // 31x31 box sum = prefix difference of vertical sums
                const float h   = sP[j][i + 15] - sP[j][i - 16];
                const float avg = h * (1.0f / 961.0f);

                const float tv = tt[j];
                const float w  = 1.0f + 5.0f * fabsf(avg - tv);

                const float xv = xx[j];
                const float ax = fabsf(xv);
                const float e  = __expf(-ax);            // MUFU EX2
                const float d  = 1.0f + e;               // in (1, 2]
                const float L  = __logf(d);              // log1p(exp(-|x|))

                // fast reciprocal of d in (1,2]: bit-hack + 2 Newton (err ~6e-6)
                float rcp = __uint_as_float(0x7EF311C3u - __float_as_uint(d));
                rcp = rcp * (2.0f - d * rcp);
                rcp = rcp * (2.0f - d * rcp);

                const float bce = fmaxf(xv, 0.0f) - xv * tv + L;
                const float p   = (xv >= 0.0f) ? rcp : e * rcp;   // sigmoid(x)

                a_wb += w * bce;
                a_w  += w;
                a_i  += p * tv * w;
                a_u  += (p + tv) * w;
            }
        }

        // ---- rotate prefetch registers ----
        if (batch + 1 < NB) {
            #pragma unroll
            for (int j = 0; j < RB; ++j) {
                tn[j] = ntn[j]; to[j] = nto[j]; tt[j] = ntt[j]; xx[j] = nxx[j];
            }
        }
    }
    #undef LDT

    // ---- block reduction of the 4 accumulators ----
    float vals[4] = {a_wb, a_w, a_i, a_u};
    #pragma unroll
    for (int k = 0; k < 4; ++k) {
        float v = vals[k];
        #pragma unroll
        for (int o = 16; o > 0; o >>= 1)
            v += __shfl_down_sync(0xffffffffu, v, o);
        vals[k] = v;
    }
    if (lid == 0) {
        #pragma unroll
        for (int k = 0; k < 4; ++k) rsum[wid][k] = vals[k];
    }
    __syncthreads();
    if (i == 0) {
        #pragma unroll
        for (int k = 0; k < 4; ++k) {
            float s2 = rsum[0][k] + rsum[1][k] + rsum[2][k] + rsum[3][k] + rsum[4][k];
            atomicAdd(&g_acc[b * 4 + k], s2);
        }
    }
}

__global__ void finalize_kernel(float* __restrict__ out) {
    const int b = threadIdx.x;   // 32 threads, one per image
    float v = 0.0f;
    if (b < BATCH) {
        const float swb = g_acc[b * 4 + 0];
        const float sw  = g_acc[b * 4 + 1];
        const float si  = g_acc[b * 4 + 2];
        const float su  = g_acc[b * 4 + 3];
        const float wbce = swb / sw;
        const float wiou = 1.0f - (si + 1.0f) / (su - si + 1.0f);
        v = wbce + wiou;
    }
    #pragma unroll
    for (int o = 16; o > 0; o >>= 1)
        v += __shfl_down_sync(0xffffffffu, v, o);
    if (b == 0) out[0] = v * (1.0f / (float)BATCH);
}

extern "C" void kernel_launch(void* const* d_in, const int* in_sizes, int n_in,
                              void* d_out, int out_size)
{
    const float* x = (const float*)d_in[0];   // input (logits)
    const float* t = (const float*)d_in[1];   // target
    float* out = (float*)d_out;

    zero_acc_kernel<<<1, 128>>>();
    dim3 grid(Wdim / TW, Hdim / SEG, BATCH);  // (4, 8, 32)
    structloss_main<<<grid, NT>>>(x, t);
    finalize_kernel<<<1, 32>>>(out);
}